// round 2
// baseline (speedup 1.0000x reference)
#include <cuda_runtime.h>
#include <math.h>

#define SEQ    2048
#define DMODEL 2048

#define NEGINF (-1e30f)

// ---------------- scratch ----------------
__device__ float g_q[SEQ * 128];          // tanh(q proj)  [S][H*8]
__device__ float g_k[SEQ * 32];           // tanh(k proj)  [S][KV*8]
__device__ float g_v[SEQ * 32];           // sigmoid(v)    [S][KV*8]
__device__ float g_attn[SEQ * 128];       // attention out [S][H*8]
__device__ float g_part[8 * SEQ * 192];   // split-K partials [kz][m][n]

// ---------------- Pass A1: split-K QKV projection partials ----------------
// part[kz][m][n] = sum_{k in chunk kz} X[m][k] * W[n][k]
// M=2048, N=192 (128 q | 32 k | 32 v), K=2048 split into 8 chunks of 256.
__global__ __launch_bounds__(256) void proj_partial(
    const float* __restrict__ X,
    const float* __restrict__ Wq,
    const float* __restrict__ Wk,
    const float* __restrict__ Wv)
{
    __shared__ float As[16][132];   // [k][m] transposed
    __shared__ float Bs[16][68];    // [k][n]
    const int m0 = blockIdx.x * 128;
    const int n0 = blockIdx.y * 64;
    const int kz = blockIdx.z;
    const int kbase = kz * 256;
    const int t = threadIdx.x;

    // loader mapping
    const int arow = t >> 1;               // 0..127
    const int akA  = (t & 1) * 4;          // first float4 k-offset (second at +8)
    const int brow = t >> 2;               // 0..63
    const int bk   = (t & 3) * 4;
    const float* xr = X + (size_t)(m0 + arow) * DMODEL + kbase;
    const int gn = n0 + brow;
    const float* wr;
    if (gn < 128)      wr = Wq + (size_t)gn * DMODEL;
    else if (gn < 160) wr = Wk + (size_t)(gn - 128) * DMODEL;
    else               wr = Wv + (size_t)(gn - 160) * DMODEL;
    wr += kbase;

    // compute mapping: 16x16 thread grid, 8x4 micro-tile
    const int tyy = t >> 4, txx = t & 15;
    const int i0 = tyy * 8, j0 = txx * 4;

    float acc[8][4] = {};
    for (int k0 = 0; k0 < 256; k0 += 16) {
        const float4 a0 = *(const float4*)(xr + k0 + akA);
        const float4 a1 = *(const float4*)(xr + k0 + akA + 8);
        const float4 b0 = *(const float4*)(wr + k0 + bk);
        __syncthreads();
        As[akA + 0][arow] = a0.x; As[akA + 1][arow] = a0.y;
        As[akA + 2][arow] = a0.z; As[akA + 3][arow] = a0.w;
        As[akA + 8][arow] = a1.x; As[akA + 9][arow] = a1.y;
        As[akA +10][arow] = a1.z; As[akA +11][arow] = a1.w;
        Bs[bk + 0][brow] = b0.x; Bs[bk + 1][brow] = b0.y;
        Bs[bk + 2][brow] = b0.z; Bs[bk + 3][brow] = b0.w;
        __syncthreads();
        #pragma unroll
        for (int kk = 0; kk < 16; ++kk) {
            const float4 av0 = *(const float4*)&As[kk][i0];
            const float4 av1 = *(const float4*)&As[kk][i0 + 4];
            const float4 bv  = *(const float4*)&Bs[kk][j0];
            float ar[8] = {av0.x, av0.y, av0.z, av0.w, av1.x, av1.y, av1.z, av1.w};
            float br[4] = {bv.x, bv.y, bv.z, bv.w};
            #pragma unroll
            for (int i = 0; i < 8; ++i)
                #pragma unroll
                for (int j = 0; j < 4; ++j)
                    acc[i][j] = fmaf(ar[i], br[j], acc[i][j]);
        }
    }
    #pragma unroll
    for (int i = 0; i < 8; ++i) {
        float4 o = make_float4(acc[i][0], acc[i][1], acc[i][2], acc[i][3]);
        *(float4*)&g_part[((size_t)kz * SEQ + (m0 + i0 + i)) * 192 + n0 + j0] = o;
    }
}

// ---------------- Pass A2: reduce partials + activations ----------------
__global__ __launch_bounds__(256) void proj_reduce(const float* __restrict__ tau)
{
    const int idx = blockIdx.x * 256 + threadIdx.x;   // 0 .. 2048*192-1
    const float inv_tau = 1.0f / tau[0];
    float s = 0.0f;
    #pragma unroll
    for (int p = 0; p < 8; ++p) s += g_part[(size_t)p * (SEQ * 192) + idx];
    const int m = idx / 192;
    const int n = idx - m * 192;
    const float x = s * inv_tau;
    if (n < 128)      g_q[m * 128 + n]        = tanhf(x);
    else if (n < 160) g_k[m * 32 + (n - 128)] = tanhf(x);
    else              g_v[m * 32 + (n - 160)] = 1.0f / (1.0f + expf(-x));
}

// ---------------- Pass B: fused suffix attention ----------------
// CTA = (head h, query block of 64). Score via diagonal-band prefix:
//   score(q,k) = (D[a+31][b+31] - D[a-1][b-1]) * scale + k/(q+1)/tau,  k < q
// G[i,j] = dot8(q8[i], k8[j]) on 96x96 halo tile; D = diagonal prefix of G.
__global__ __launch_bounds__(256, 3) void attn_kernel(const float* __restrict__ tau)
{
    __shared__ float qs[96 * 8];      // q halo rows, stride 8
    __shared__ float ks[96 * 10];     // k halo rows, stride 10 (8B-aligned, low-conflict)
    __shared__ float vsm[64 * 8];     // shifted v rows
    __shared__ float G[96 * 100];     // G then D in place (stride 100)

    const int h  = blockIdx.y;
    const int qb = 31 - blockIdx.x;   // big blocks first
    const int q0 = qb * 64;
    const int c  = h >> 2;            // GQA kv head
    const int t  = threadIdx.x;
    const int w  = t >> 5, lane = t & 31;
    const float inv_tau = 1.0f / tau[0];
    const float scale   = 0.0625f * inv_tau;

    // q halo: rows q0-31 .. q0+64
    if (t < 192) {
        const int r = t >> 1, half = t & 1;
        const int gq = q0 - 31 + r;
        float4 v4 = make_float4(0.f, 0.f, 0.f, 0.f);
        if (gq >= 0 && gq < SEQ) v4 = *(const float4*)&g_q[gq * 128 + h * 8 + half * 4];
        *(float4*)&qs[r * 8 + half * 4] = v4;
    }

    const int a  = t >> 2;            // query row (0..63)
    const int jq = t & 3;             // 4 threads per row
    const int qg = q0 + a;
    const float bias_r = inv_tau / (float)(qg + 1);

    float m_run = NEGINF, l_run = 0.0f;
    float acc[8];
    #pragma unroll
    for (int d = 0; d < 8; ++d) acc[d] = 0.0f;

    const int ty = t >> 4, tx = t & 15;
    const int i0 = ty * 6, j0 = tx * 6;

    for (int kb = 0; kb <= qb; ++kb) {
        const int k0 = kb * 64;
        __syncthreads();   // previous stage done with ks/vsm/G

        // load k halo + shifted v
        if (t < 192) {
            const int r = t >> 1, half = t & 1;
            const int gk = k0 - 31 + r;
            float4 v4 = make_float4(0.f, 0.f, 0.f, 0.f);
            if (gk >= 0 && gk < SEQ) v4 = *(const float4*)&g_k[gk * 32 + c * 8 + half * 4];
            float* p = &ks[r * 10 + half * 4];
            *(float2*)(p)     = make_float2(v4.x, v4.y);
            *(float2*)(p + 2) = make_float2(v4.z, v4.w);
        } else {
            const int u = t - 192;
            #pragma unroll
            for (int rep = 0; rep < 2; ++rep) {
                const int idx = u * 2 + rep;
                const int r = idx >> 1, half = idx & 1;
                const int gk = k0 + r + 1;  // vs[k] = v[k+1]
                float4 v4 = make_float4(0.f, 0.f, 0.f, 0.f);
                if (gk < SEQ) v4 = *(const float4*)&g_v[gk * 32 + c * 8 + half * 4];
                *(float4*)&vsm[r * 8 + half * 4] = v4;
            }
        }
        __syncthreads();

        // G compute: 6x6 block per thread, d in float2 pairs
        {
            float gacc[6][6] = {};
            #pragma unroll
            for (int dp = 0; dp < 4; ++dp) {
                float2 qd[6], kd[6];
                #pragma unroll
                for (int ii = 0; ii < 6; ++ii)
                    qd[ii] = *(const float2*)&qs[(i0 + ii) * 8 + dp * 2];
                #pragma unroll
                for (int jj = 0; jj < 6; ++jj)
                    kd[jj] = *(const float2*)&ks[(j0 + jj) * 10 + dp * 2];
                #pragma unroll
                for (int ii = 0; ii < 6; ++ii)
                    #pragma unroll
                    for (int jj = 0; jj < 6; ++jj) {
                        gacc[ii][jj] = fmaf(qd[ii].x, kd[jj].x, gacc[ii][jj]);
                        gacc[ii][jj] = fmaf(qd[ii].y, kd[jj].y, gacc[ii][jj]);
                    }
            }
            #pragma unroll
            for (int ii = 0; ii < 6; ++ii)
                #pragma unroll
                for (int jj = 0; jj < 6; ++jj)
                    G[(i0 + ii) * 100 + (j0 + jj)] = gacc[ii][jj];
        }
        __syncthreads();

        // diagonal prefix D[i][j] = G[i][j] + D[i-1][j-1], warp-scan per diagonal
        for (int dIdx = w; dIdx < 191; dIdx += 8) {
            const int dlt = dIdx - 95;
            const int ad  = dlt < 0 ? -dlt : dlt;
            const int L   = 96 - ad;
            const int base = (dlt > 0) ? dlt * 100 : -dlt;
            const int e0i = 3 * lane;
            float e0 = (e0i     < L) ? G[base + (e0i    ) * 101] : 0.0f;
            float e1 = (e0i + 1 < L) ? G[base + (e0i + 1) * 101] : 0.0f;
            float e2 = (e0i + 2 < L) ? G[base + (e0i + 2) * 101] : 0.0f;
            const float p1 = e0 + e1;
            const float p2 = p1 + e2;
            float s = p2;
            #pragma unroll
            for (int o = 1; o < 32; o <<= 1) {
                const float v = __shfl_up_sync(0xffffffffu, s, o);
                if (lane >= o) s += v;
            }
            const float off = s - p2;   // exclusive prefix of thread blocks
            if (e0i     < L) G[base + (e0i    ) * 101] = e0 + off;
            if (e0i + 1 < L) G[base + (e0i + 1) * 101] = p1 + off;
            if (e0i + 2 < L) G[base + (e0i + 2) * 101] = p2 + off;
        }
        __syncthreads();

        // two-pass online softmax; each thread: k = k0 + jq + 4*bb
        const int browH = (a + 31) * 100 + 31;
        const int browL = (a - 1) * 100 - 1;
        float tmax = NEGINF;
        #pragma unroll
        for (int bb = 0; bb < 16; ++bb) {
            const int b  = (bb << 2) | jq;
            const int kg = k0 + b;
            if (kg < qg) {
                const float hi = G[browH + b];
                const float lo = (a > 0 && b > 0) ? G[browL + b] : 0.0f;
                const float s2 = (hi - lo) * scale + (float)kg * bias_r;
                tmax = fmaxf(tmax, s2);
            }
        }
        if (tmax > NEGINF) {
            const float nm = fmaxf(m_run, tmax);
            if (m_run > NEGINF && nm > m_run) {
                const float f = __expf(m_run - nm);
                l_run *= f;
                #pragma unroll
                for (int d = 0; d < 8; ++d) acc[d] *= f;
            }
            m_run = nm;
            #pragma unroll
            for (int bb = 0; bb < 16; ++bb) {
                const int b  = (bb << 2) | jq;
                const int kg = k0 + b;
                if (kg < qg) {
                    const float hi = G[browH + b];
                    const float lo = (a > 0 && b > 0) ? G[browL + b] : 0.0f;
                    const float s2 = (hi - lo) * scale + (float)kg * bias_r;
                    const float e = __expf(s2 - m_run);
                    l_run += e;
                    const float4 v0 = *(const float4*)&vsm[b * 8];
                    const float4 v1 = *(const float4*)&vsm[b * 8 + 4];
                    acc[0] = fmaf(e, v0.x, acc[0]); acc[1] = fmaf(e, v0.y, acc[1]);
                    acc[2] = fmaf(e, v0.z, acc[2]); acc[3] = fmaf(e, v0.w, acc[3]);
                    acc[4] = fmaf(e, v1.x, acc[4]); acc[5] = fmaf(e, v1.y, acc[5]);
                    acc[6] = fmaf(e, v1.z, acc[6]); acc[7] = fmaf(e, v1.w, acc[7]);
                }
            }
        }
    }

    // merge the 4 threads of each query row
    #pragma unroll
    for (int off = 1; off < 4; off <<= 1) {
        const float mo  = __shfl_xor_sync(0xffffffffu, m_run, off);
        const float lo2 = __shfl_xor_sync(0xffffffffu, l_run, off);
        const float nm = fmaxf(m_run, mo);
        const float f1 = (m_run > NEGINF) ? __expf(m_run - nm) : 0.0f;
        const float f2 = (mo    > NEGINF) ? __expf(mo    - nm) : 0.0f;
        l_run = l_run * f1 + lo2 * f2;
        #pragma unroll
        for (int d = 0; d < 8; ++d) {
            const float ao = __shfl_xor_sync(0xffffffffu, acc[d], off);
            acc[d] = acc[d] * f1 + ao * f2;
        }
        m_run = nm;
    }
    if (jq == 0) {
        const float invl = (l_run > 0.0f) ? 1.0f / l_run : 0.0f;
        #pragma unroll
        for (int d = 0; d < 8; ++d)
            g_attn[qg * 128 + h * 8 + d] = acc[d] * invl;
    }
}

// ---------------- Pass C: affine + output projection ----------------
__global__ __launch_bounds__(256) void out_kernel(
    const float* __restrict__ Wo,
    const float* __restrict__ ve0,
    const float* __restrict__ ve1,
    float* __restrict__ out)
{
    __shared__ float As[16][68];
    __shared__ float Bs[16][68];
    const int m0 = blockIdx.x * 64;
    const int n0 = blockIdx.y * 64;
    const int t  = threadIdx.x;
    const int lm  = t >> 2;
    const int lk4 = (t & 3) << 2;
    const int mm  = (t >> 4) << 2;
    const int nn  = (t & 15) << 2;

    const float* arow = g_attn + (m0 + lm) * 128;
    const float* brow = Wo + (n0 + lm) * 128;

    float acc[4][4] = {};
    for (int k0 = 0; k0 < 128; k0 += 16) {
        float4 av = *(const float4*)(arow + k0 + lk4);
        const float4 e0 = *(const float4*)(ve0 + k0 + lk4);
        const float4 e1 = *(const float4*)(ve1 + k0 + lk4);
        av.x = av.x * (e1.x - e0.x) + e0.x;
        av.y = av.y * (e1.y - e0.y) + e0.y;
        av.z = av.z * (e1.z - e0.z) + e0.z;
        av.w = av.w * (e1.w - e0.w) + e0.w;
        const float4 bv = *(const float4*)(brow + k0 + lk4);
        As[lk4 + 0][lm] = av.x; As[lk4 + 1][lm] = av.y;
        As[lk4 + 2][lm] = av.z; As[lk4 + 3][lm] = av.w;
        Bs[lk4 + 0][lm] = bv.x; Bs[lk4 + 1][lm] = bv.y;
        Bs[lk4 + 2][lm] = bv.z; Bs[lk4 + 3][lm] = bv.w;
        __syncthreads();
        #pragma unroll
        for (int kk = 0; kk < 16; ++kk) {
            float4 a4 = *(const float4*)&As[kk][mm];
            float4 b4 = *(const float4*)&Bs[kk][nn];
            float ar[4] = {a4.x, a4.y, a4.z, a4.w};
            float br[4] = {b4.x, b4.y, b4.z, b4.w};
            #pragma unroll
            for (int i = 0; i < 4; ++i)
                #pragma unroll
                for (int j = 0; j < 4; ++j)
                    acc[i][j] = fmaf(ar[i], br[j], acc[i][j]);
        }
        __syncthreads();
    }
    #pragma unroll
    for (int i = 0; i < 4; ++i)
        #pragma unroll
        for (int j = 0; j < 4; ++j)
            out[(m0 + mm + i) * DMODEL + (n0 + nn + j)] = acc[i][j];
}

// ---------------- launch ----------------
extern "C" void kernel_launch(void* const* d_in, const int* in_sizes, int n_in,
                              void* d_out, int out_size)
{
    const float* X   = (const float*)d_in[0];
    const float* Wq  = (const float*)d_in[1];
    const float* Wk  = (const float*)d_in[2];
    const float* Wv  = (const float*)d_in[3];
    const float* Wo  = (const float*)d_in[4];
    const float* ve0 = (const float*)d_in[5];
    const float* ve1 = (const float*)d_in[6];
    const float* tau = (const float*)d_in[7];
    float* out = (float*)d_out;
    (void)in_sizes; (void)n_in; (void)out_size;

    proj_partial<<<dim3(16, 3, 8), 256>>>(X, Wq, Wk, Wv);
    proj_reduce <<<1536, 256>>>(tau);
    attn_kernel <<<dim3(32, 16), 256>>>(tau);
    out_kernel  <<<dim3(32, 32), 256>>>(Wo, ve0, ve1, out);
}

// round 4
// speedup vs baseline: 1.3111x; 1.3111x over previous
#include <cuda_runtime.h>
#include <math.h>

#define SEQ    2048
#define DMODEL 2048

#define NEGINF (-1e30f)

// ---------------- scratch ----------------
__device__ float g_q[SEQ * 128];          // tanh(q proj)  [S][H*8]
__device__ float g_k[SEQ * 32];           // tanh(k proj)  [S][KV*8]
__device__ float g_v[SEQ * 32];           // sigmoid(v)    [S][KV*8]
__device__ float g_attn[SEQ * 128];       // attention out [S][H*8]
__device__ float g_part[8 * SEQ * 192];   // split-K partials [kz][m][n]

// attn dynamic smem layout (floats)
#define QS_OFF   0                        // 96*8   = 768
#define KS_OFF   768                      // 2*96*10 = 1920
#define VS_OFF   (768 + 1920)             // 2*64*8  = 1024
#define G_OFF    (768 + 1920 + 1024)      // 96*100  = 9600
#define SMEM_FLOATS (G_OFF + 9600)        // 13312 floats = 53248 B

// ---------------- Pass A1: split-K QKV projection partials ----------------
__global__ __launch_bounds__(256) void proj_partial(
    const float* __restrict__ X,
    const float* __restrict__ Wq,
    const float* __restrict__ Wk,
    const float* __restrict__ Wv)
{
    __shared__ float As[16][132];   // [k][m] transposed
    __shared__ float Bs[16][68];    // [k][n]
    const int m0 = blockIdx.x * 128;
    const int n0 = blockIdx.y * 64;
    const int kz = blockIdx.z;
    const int kbase = kz * 256;
    const int t = threadIdx.x;

    const int arow = t >> 1;
    const int akA  = (t & 1) * 4;
    const int brow = t >> 2;
    const int bk   = (t & 3) * 4;
    const float* xr = X + (size_t)(m0 + arow) * DMODEL + kbase;
    const int gn = n0 + brow;
    const float* wr;
    if (gn < 128)      wr = Wq + (size_t)gn * DMODEL;
    else if (gn < 160) wr = Wk + (size_t)(gn - 128) * DMODEL;
    else               wr = Wv + (size_t)(gn - 160) * DMODEL;
    wr += kbase;

    const int tyy = t >> 4, txx = t & 15;
    const int i0 = tyy * 8, j0 = txx * 4;

    float acc[8][4] = {};
    for (int k0 = 0; k0 < 256; k0 += 16) {
        const float4 a0 = *(const float4*)(xr + k0 + akA);
        const float4 a1 = *(const float4*)(xr + k0 + akA + 8);
        const float4 b0 = *(const float4*)(wr + k0 + bk);
        __syncthreads();
        As[akA + 0][arow] = a0.x; As[akA + 1][arow] = a0.y;
        As[akA + 2][arow] = a0.z; As[akA + 3][arow] = a0.w;
        As[akA + 8][arow] = a1.x; As[akA + 9][arow] = a1.y;
        As[akA +10][arow] = a1.z; As[akA +11][arow] = a1.w;
        Bs[bk + 0][brow] = b0.x; Bs[bk + 1][brow] = b0.y;
        Bs[bk + 2][brow] = b0.z; Bs[bk + 3][brow] = b0.w;
        __syncthreads();
        #pragma unroll
        for (int kk = 0; kk < 16; ++kk) {
            const float4 av0 = *(const float4*)&As[kk][i0];
            const float4 av1 = *(const float4*)&As[kk][i0 + 4];
            const float4 bv  = *(const float4*)&Bs[kk][j0];
            float ar[8] = {av0.x, av0.y, av0.z, av0.w, av1.x, av1.y, av1.z, av1.w};
            float br[4] = {bv.x, bv.y, bv.z, bv.w};
            #pragma unroll
            for (int i = 0; i < 8; ++i)
                #pragma unroll
                for (int j = 0; j < 4; ++j)
                    acc[i][j] = fmaf(ar[i], br[j], acc[i][j]);
        }
    }
    #pragma unroll
    for (int i = 0; i < 8; ++i) {
        float4 o = make_float4(acc[i][0], acc[i][1], acc[i][2], acc[i][3]);
        *(float4*)&g_part[((size_t)kz * SEQ + (m0 + i0 + i)) * 192 + n0 + j0] = o;
    }
}

// ---------------- Pass A2: reduce partials + activations ----------------
__global__ __launch_bounds__(256) void proj_reduce(const float* __restrict__ tau)
{
    const int idx = blockIdx.x * 256 + threadIdx.x;
    const float inv_tau = 1.0f / tau[0];
    float s = 0.0f;
    #pragma unroll
    for (int p = 0; p < 8; ++p) s += g_part[(size_t)p * (SEQ * 192) + idx];
    const int m = idx / 192;
    const int n = idx - m * 192;
    const float x = s * inv_tau;
    if (n < 128)      g_q[m * 128 + n]        = tanhf(x);
    else if (n < 160) g_k[m * 32 + (n - 128)] = tanhf(x);
    else              g_v[m * 32 + (n - 160)] = 1.0f / (1.0f + expf(-x));
}

// ---------------- Pass B: fused suffix attention ----------------
// CTA = (head h, query block of 64). Score via diagonal-band prefix:
//   score(q,k) = (D[a+31][b+31] - D[a-1][b-1]) * scale + k/(q+1)/tau, k < q
// Double-buffered k/v tiles; single-pass softmax; unroll-4 serial prefix.
__global__ __launch_bounds__(256) void attn_kernel(const float* __restrict__ tau)
{
    extern __shared__ float smem[];
    float* qs  = smem + QS_OFF;           // [96][8]
    float* ksb = smem + KS_OFF;           // [2][96*10]
    float* vsb = smem + VS_OFF;           // [2][64*8]
    float* G   = smem + G_OFF;            // [96][100]

    const int h  = blockIdx.y;
    const int qb = 31 - blockIdx.x;       // big blocks first
    const int q0 = qb * 64;
    const int c  = h >> 2;                // GQA kv head
    const int t  = threadIdx.x;
    const float inv_tau = 1.0f / tau[0];
    const float scale   = 0.0625f * inv_tau;

    // q halo: rows q0-31 .. q0+64
    if (t < 192) {
        const int r = t >> 1, half = t & 1;
        const int gq = q0 - 31 + r;
        float4 v4 = make_float4(0.f, 0.f, 0.f, 0.f);
        if (gq >= 0 && gq < SEQ) v4 = *(const float4*)&g_q[gq * 128 + h * 8 + half * 4];
        *(float4*)&qs[r * 8 + half * 4] = v4;
    }

    const int a  = t >> 2;                // query row (0..63)
    const int jq = t & 3;                 // 4 threads per row
    const int qg = q0 + a;
    const float bias_r = inv_tau / (float)(qg + 1);

    float m_run = NEGINF, l_run = 0.0f;
    float acc[8];
    #pragma unroll
    for (int d = 0; d < 8; ++d) acc[d] = 0.0f;

    const int ty = t >> 4, tx = t & 15;
    const int i0 = ty * 6, j0 = tx * 6;

    // loader mapping
    const int lr = t >> 1, lhalf = t & 1;     // t < 192: k halo
    const int lu = t - 192;                   // t >= 192: v rows

    // ---- preload tile 0 into buffer 0 ----
    {
        if (t < 192) {
            const int gk = -31 + lr;
            float4 v4 = make_float4(0.f, 0.f, 0.f, 0.f);
            if (gk >= 0) v4 = *(const float4*)&g_k[gk * 32 + c * 8 + lhalf * 4];
            float* p = &ksb[lr * 10 + lhalf * 4];
            *(float2*)(p)     = make_float2(v4.x, v4.y);
            *(float2*)(p + 2) = make_float2(v4.z, v4.w);
        } else {
            #pragma unroll
            for (int rep = 0; rep < 2; ++rep) {
                const int idx = lu * 2 + rep;
                const int r = idx >> 1, half = idx & 1;
                const int gk = r + 1;
                float4 v4 = *(const float4*)&g_v[gk * 32 + c * 8 + half * 4];
                *(float4*)&vsb[r * 8 + half * 4] = v4;
            }
        }
    }

    for (int kb = 0; kb <= qb; ++kb) {
        const int k0 = kb * 64;
        const int buf = kb & 1;
        const float* ks  = ksb + buf * 960;
        const float* vsm = vsb + buf * 512;
        __syncthreads();   // loads for this tile done; prev score done with G

        // ---- G compute: 6x6 block per thread, d in float2 pairs ----
        {
            float gacc[6][6] = {};
            #pragma unroll
            for (int dp = 0; dp < 4; ++dp) {
                float2 qd[6], kd[6];
                #pragma unroll
                for (int ii = 0; ii < 6; ++ii)
                    qd[ii] = *(const float2*)&qs[(i0 + ii) * 8 + dp * 2];
                #pragma unroll
                for (int jj = 0; jj < 6; ++jj)
                    kd[jj] = *(const float2*)&ks[(j0 + jj) * 10 + dp * 2];
                #pragma unroll
                for (int ii = 0; ii < 6; ++ii)
                    #pragma unroll
                    for (int jj = 0; jj < 6; ++jj) {
                        gacc[ii][jj] = fmaf(qd[ii].x, kd[jj].x, gacc[ii][jj]);
                        gacc[ii][jj] = fmaf(qd[ii].y, kd[jj].y, gacc[ii][jj]);
                    }
            }
            #pragma unroll
            for (int ii = 0; ii < 6; ++ii)
                #pragma unroll
                for (int jj = 0; jj < 6; ++jj)
                    G[(i0 + ii) * 100 + (j0 + jj)] = gacc[ii][jj];
        }
        __syncthreads();

        // ---- diagonal prefix, one diagonal per thread, unroll-4 chain ----
        if (t < 191) {
            const int dlt = t - 95;
            const int ad  = dlt < 0 ? -dlt : dlt;
            const int L   = 96 - ad;
            int off = (dlt > 0) ? dlt * 100 : -dlt;
            float carry = 0.0f;
            int s = 0;
            for (; s + 4 <= L; s += 4) {
                const float e0 = G[off];
                const float e1 = G[off + 101];
                const float e2 = G[off + 202];
                const float e3 = G[off + 303];
                const float c0 = carry + e0;
                const float c1 = c0 + e1;
                const float c2 = c1 + e2;
                const float c3 = c2 + e3;
                G[off] = c0; G[off + 101] = c1; G[off + 202] = c2; G[off + 303] = c3;
                carry = c3;
                off += 404;
            }
            for (; s < L; ++s) { carry += G[off]; G[off] = carry; off += 101; }
        }
        __syncthreads();

        // ---- prefetch next tile into other buffer (overlaps score phase) ----
        if (kb < qb) {
            const int nk0 = k0 + 64;
            if (t < 192) {
                const int gk = nk0 - 31 + lr;
                const float4 v4 = *(const float4*)&g_k[gk * 32 + c * 8 + lhalf * 4];
                float* p = &ksb[(buf ^ 1) * 960 + lr * 10 + lhalf * 4];
                *(float2*)(p)     = make_float2(v4.x, v4.y);
                *(float2*)(p + 2) = make_float2(v4.z, v4.w);
            } else {
                #pragma unroll
                for (int rep = 0; rep < 2; ++rep) {
                    const int idx = lu * 2 + rep;
                    const int r = idx >> 1, half = idx & 1;
                    const int gk = nk0 + r + 1;
                    float4 v4 = make_float4(0.f, 0.f, 0.f, 0.f);
                    if (gk < SEQ) v4 = *(const float4*)&g_v[gk * 32 + c * 8 + half * 4];
                    *(float4*)&vsb[(buf ^ 1) * 512 + r * 8 + half * 4] = v4;
                }
            }
        }

        // ---- scores + single-pass online softmax ----
        float sv[16];
        float tmax = NEGINF;
        const int browH = (a + 31) * 100 + 31;
        const int browL = (a - 1) * 100 - 1;
        #pragma unroll
        for (int bb = 0; bb < 16; ++bb) {
            const int b  = (bb << 2) | jq;
            const int kg = k0 + b;
            float s = NEGINF;
            if (kg < qg) {
                const float hi = G[browH + b];
                const float lo = (a > 0 && b > 0) ? G[browL + b] : 0.0f;
                s = (hi - lo) * scale + (float)kg * bias_r;
            }
            sv[bb] = s;
            tmax = fmaxf(tmax, s);
        }
        if (tmax > NEGINF) {
            const float nm = fmaxf(m_run, tmax);
            if (m_run > NEGINF && nm > m_run) {
                const float f = __expf(m_run - nm);
                l_run *= f;
                #pragma unroll
                for (int d = 0; d < 8; ++d) acc[d] *= f;
            }
            m_run = nm;
            #pragma unroll
            for (int bb = 0; bb < 16; ++bb) {
                if (sv[bb] > NEGINF) {
                    const float e = __expf(sv[bb] - m_run);
                    l_run += e;
                    const int b = (bb << 2) | jq;
                    const float4 v0 = *(const float4*)&vsm[b * 8];
                    const float4 v1 = *(const float4*)&vsm[b * 8 + 4];
                    acc[0] = fmaf(e, v0.x, acc[0]); acc[1] = fmaf(e, v0.y, acc[1]);
                    acc[2] = fmaf(e, v0.z, acc[2]); acc[3] = fmaf(e, v0.w, acc[3]);
                    acc[4] = fmaf(e, v1.x, acc[4]); acc[5] = fmaf(e, v1.y, acc[5]);
                    acc[6] = fmaf(e, v1.z, acc[6]); acc[7] = fmaf(e, v1.w, acc[7]);
                }
            }
        }
    }

    // merge the 4 threads of each query row
    #pragma unroll
    for (int off = 1; off < 4; off <<= 1) {
        const float mo  = __shfl_xor_sync(0xffffffffu, m_run, off);
        const float lo2 = __shfl_xor_sync(0xffffffffu, l_run, off);
        const float nm = fmaxf(m_run, mo);
        const float f1 = (m_run > NEGINF) ? __expf(m_run - nm) : 0.0f;
        const float f2 = (mo    > NEGINF) ? __expf(mo    - nm) : 0.0f;
        l_run = l_run * f1 + lo2 * f2;
        #pragma unroll
        for (int d = 0; d < 8; ++d) {
            const float ao = __shfl_xor_sync(0xffffffffu, acc[d], off);
            acc[d] = acc[d] * f1 + ao * f2;
        }
        m_run = nm;
    }
    if (jq == 0) {
        const float invl = (l_run > 0.0f) ? 1.0f / l_run : 0.0f;
        #pragma unroll
        for (int d = 0; d < 8; ++d)
            g_attn[qg * 128 + h * 8 + d] = acc[d] * invl;
    }
}

// ---------------- Pass C: affine + output projection ----------------
__global__ __launch_bounds__(256) void out_kernel(
    const float* __restrict__ Wo,
    const float* __restrict__ ve0,
    const float* __restrict__ ve1,
    float* __restrict__ out)
{
    __shared__ float As[16][68];
    __shared__ float Bs[16][68];
    const int m0 = blockIdx.x * 64;
    const int n0 = blockIdx.y * 64;
    const int t  = threadIdx.x;
    const int lm  = t >> 2;
    const int lk4 = (t & 3) << 2;
    const int mm  = (t >> 4) << 2;
    const int nn  = (t & 15) << 2;

    const float* arow = g_attn + (m0 + lm) * 128;
    const float* brow = Wo + (n0 + lm) * 128;

    float acc[4][4] = {};
    for (int k0 = 0; k0 < 128; k0 += 16) {
        float4 av = *(const float4*)(arow + k0 + lk4);
        const float4 e0 = *(const float4*)(ve0 + k0 + lk4);
        const float4 e1 = *(const float4*)(ve1 + k0 + lk4);
        av.x = av.x * (e1.x - e0.x) + e0.x;
        av.y = av.y * (e1.y - e0.y) + e0.y;
        av.z = av.z * (e1.z - e0.z) + e0.z;
        av.w = av.w * (e1.w - e0.w) + e0.w;
        const float4 bv = *(const float4*)(brow + k0 + lk4);
        As[lk4 + 0][lm] = av.x; As[lk4 + 1][lm] = av.y;
        As[lk4 + 2][lm] = av.z; As[lk4 + 3][lm] = av.w;
        Bs[lk4 + 0][lm] = bv.x; Bs[lk4 + 1][lm] = bv.y;
        Bs[lk4 + 2][lm] = bv.z; Bs[lk4 + 3][lm] = bv.w;
        __syncthreads();
        #pragma unroll
        for (int kk = 0; kk < 16; ++kk) {
            float4 a4 = *(const float4*)&As[kk][mm];
            float4 b4 = *(const float4*)&Bs[kk][nn];
            float ar[4] = {a4.x, a4.y, a4.z, a4.w};
            float br[4] = {b4.x, b4.y, b4.z, b4.w};
            #pragma unroll
            for (int i = 0; i < 4; ++i)
                #pragma unroll
                for (int j = 0; j < 4; ++j)
                    acc[i][j] = fmaf(ar[i], br[j], acc[i][j]);
        }
        __syncthreads();
    }
    #pragma unroll
    for (int i = 0; i < 4; ++i)
        #pragma unroll
        for (int j = 0; j < 4; ++j)
            out[(m0 + mm + i) * DMODEL + (n0 + nn + j)] = acc[i][j];
}

// ---------------- launch ----------------
extern "C" void kernel_launch(void* const* d_in, const int* in_sizes, int n_in,
                              void* d_out, int out_size)
{
    const float* X   = (const float*)d_in[0];
    const float* Wq  = (const float*)d_in[1];
    const float* Wk  = (const float*)d_in[2];
    const float* Wv  = (const float*)d_in[3];
    const float* Wo  = (const float*)d_in[4];
    const float* ve0 = (const float*)d_in[5];
    const float* ve1 = (const float*)d_in[6];
    const float* tau = (const float*)d_in[7];
    float* out = (float*)d_out;
    (void)in_sizes; (void)n_in; (void)out_size;

    cudaFuncSetAttribute(attn_kernel,
                         cudaFuncAttributeMaxDynamicSharedMemorySize,
                         SMEM_FLOATS * (int)sizeof(float));

    proj_partial<<<dim3(16, 3, 8), 256>>>(X, Wq, Wk, Wv);
    proj_reduce <<<1536, 256>>>(tau);
    attn_kernel <<<dim3(32, 16), 256, SMEM_FLOATS * sizeof(float)>>>(tau);
    out_kernel  <<<dim3(32, 32), 256>>>(Wo, ve0, ve1, out);
}

// round 6
// speedup vs baseline: 1.4692x; 1.1206x over previous
#include <cuda_runtime.h>
#include <math.h>

#define SEQ    2048
#define DMODEL 2048

#define NEGINF (-1e30f)

// ---------------- scratch ----------------
__device__ float g_q[SEQ * 128];          // tanh(q proj)  [S][H*8]
__device__ float g_k[SEQ * 32];           // tanh(k proj)  [S][KV*8]
__device__ float g_v[SEQ * 32];           // sigmoid(v)    [S][KV*8]
__device__ float g_attn[SEQ * 128];       // affined attention out [S][H*8]
__device__ float g_part[8 * SEQ * 192];   // split-K partials [kz][m][n]

// attn dynamic smem layout (floats). G row stride = 101 so that
// diagonal-prefix lane-to-lane address stride (101) hits banks with
// step 5 (coprime 32) -> conflict-free.
#define GSTR     101
#define QS_OFF   0                        // 96*8    = 768
#define KS_OFF   768                      // 2*96*10 = 1920
#define VS_OFF   (768 + 1920)             // 2*64*8  = 1024
#define G_OFF    (768 + 1920 + 1024)      // 96*101  = 9696
#define SMEM_FLOATS (G_OFF + 96 * GSTR)   // 13408 floats = 53632 B

// ---------------- Pass A1: split-K QKV projection partials ----------------
// Pipelined: next k-tile LDGs issue before the current compute block.
__global__ __launch_bounds__(256) void proj_partial(
    const float* __restrict__ X,
    const float* __restrict__ Wq,
    const float* __restrict__ Wk,
    const float* __restrict__ Wv)
{
    __shared__ float As[16][132];   // [k][m] transposed
    __shared__ float Bs[16][68];    // [k][n]
    const int m0 = blockIdx.x * 128;
    const int n0 = blockIdx.y * 64;
    const int kz = blockIdx.z;
    const int kbase = kz * 256;
    const int t = threadIdx.x;

    const int arow = t >> 1;
    const int akA  = (t & 1) * 4;
    const int brow = t >> 2;
    const int bk   = (t & 3) * 4;
    const float* xr = X + (size_t)(m0 + arow) * DMODEL + kbase;
    const int gn = n0 + brow;
    const float* wr;
    if (gn < 128)      wr = Wq + (size_t)gn * DMODEL;
    else if (gn < 160) wr = Wk + (size_t)(gn - 128) * DMODEL;
    else               wr = Wv + (size_t)(gn - 160) * DMODEL;
    wr += kbase;

    const int tyy = t >> 4, txx = t & 15;
    const int i0 = tyy * 8, j0 = txx * 4;

    float4 a0 = *(const float4*)(xr + akA);
    float4 a1 = *(const float4*)(xr + akA + 8);
    float4 b0 = *(const float4*)(wr + bk);

    float acc[8][4] = {};
    for (int k0 = 0; k0 < 256; k0 += 16) {
        __syncthreads();
        As[akA + 0][arow] = a0.x; As[akA + 1][arow] = a0.y;
        As[akA + 2][arow] = a0.z; As[akA + 3][arow] = a0.w;
        As[akA + 8][arow] = a1.x; As[akA + 9][arow] = a1.y;
        As[akA +10][arow] = a1.z; As[akA +11][arow] = a1.w;
        Bs[bk + 0][brow] = b0.x; Bs[bk + 1][brow] = b0.y;
        Bs[bk + 2][brow] = b0.z; Bs[bk + 3][brow] = b0.w;
        __syncthreads();
        if (k0 + 16 < 256) {                 // prefetch next tile
            a0 = *(const float4*)(xr + k0 + 16 + akA);
            a1 = *(const float4*)(xr + k0 + 16 + akA + 8);
            b0 = *(const float4*)(wr + k0 + 16 + bk);
        }
        #pragma unroll
        for (int kk = 0; kk < 16; ++kk) {
            const float4 av0 = *(const float4*)&As[kk][i0];
            const float4 av1 = *(const float4*)&As[kk][i0 + 4];
            const float4 bv  = *(const float4*)&Bs[kk][j0];
            float ar[8] = {av0.x, av0.y, av0.z, av0.w, av1.x, av1.y, av1.z, av1.w};
            float br[4] = {bv.x, bv.y, bv.z, bv.w};
            #pragma unroll
            for (int i = 0; i < 8; ++i)
                #pragma unroll
                for (int j = 0; j < 4; ++j)
                    acc[i][j] = fmaf(ar[i], br[j], acc[i][j]);
        }
    }
    #pragma unroll
    for (int i = 0; i < 8; ++i) {
        float4 o = make_float4(acc[i][0], acc[i][1], acc[i][2], acc[i][3]);
        *(float4*)&g_part[((size_t)kz * SEQ + (m0 + i0 + i)) * 192 + n0 + j0] = o;
    }
}

// ---------------- Pass A2: reduce partials + activations ----------------
__global__ __launch_bounds__(256) void proj_reduce(const float* __restrict__ tau)
{
    const int idx = blockIdx.x * 256 + threadIdx.x;
    const float inv_tau = 1.0f / tau[0];
    float s = 0.0f;
    #pragma unroll
    for (int p = 0; p < 8; ++p) s += g_part[(size_t)p * (SEQ * 192) + idx];
    const int m = idx / 192;
    const int n = idx - m * 192;
    const float x = s * inv_tau;
    if (n < 128)      g_q[m * 128 + n]        = tanhf(x);
    else if (n < 160) g_k[m * 32 + (n - 128)] = tanhf(x);
    else              g_v[m * 32 + (n - 160)] = 1.0f / (1.0f + expf(-x));
}

// ---------------- Pass B: fused suffix attention ----------------
__global__ __launch_bounds__(256) void attn_kernel(
    const float* __restrict__ tau,
    const float* __restrict__ ve0,
    const float* __restrict__ ve1)
{
    extern __shared__ float smem[];
    float* qs  = smem + QS_OFF;           // [96][8]
    float* ksb = smem + KS_OFF;           // [2][96*10]
    float* vsb = smem + VS_OFF;           // [2][64*8]
    float* G   = smem + G_OFF;            // [96][GSTR]

    const int h  = blockIdx.y;
    const int qb = 31 - blockIdx.x;       // big blocks first
    const int q0 = qb * 64;
    const int c  = h >> 2;                // GQA kv head
    const int t  = threadIdx.x;
    const float inv_tau = 1.0f / tau[0];
    const float scale   = 0.0625f * inv_tau;

    // q halo: rows q0-31 .. q0+64
    if (t < 192) {
        const int r = t >> 1, half = t & 1;
        const int gq = q0 - 31 + r;
        float4 v4 = make_float4(0.f, 0.f, 0.f, 0.f);
        if (gq >= 0 && gq < SEQ) v4 = *(const float4*)&g_q[gq * 128 + h * 8 + half * 4];
        *(float4*)&qs[r * 8 + half * 4] = v4;
    }

    const int a  = t >> 2;                // query row (0..63)
    const int jq = t & 3;                 // 4 threads per row
    const int qg = q0 + a;
    const float bias_r = inv_tau / (float)(qg + 1);

    float m_run = NEGINF, l_run = 0.0f;
    float acc[8];
    #pragma unroll
    for (int d = 0; d < 8; ++d) acc[d] = 0.0f;

    const int ty = t >> 4, tx = t & 15;
    const int i0 = ty * 6, j0 = tx * 6;

    // loader mapping
    const int lr = t >> 1, lhalf = t & 1;     // t < 192: k halo
    const int lu = t - 192;                   // t >= 192: v rows

    // ---- preload tile 0 into buffer 0 ----
    {
        if (t < 192) {
            const int gk = -31 + lr;
            float4 v4 = make_float4(0.f, 0.f, 0.f, 0.f);
            if (gk >= 0) v4 = *(const float4*)&g_k[gk * 32 + c * 8 + lhalf * 4];
            float* p = &ksb[lr * 10 + lhalf * 4];
            *(float2*)(p)     = make_float2(v4.x, v4.y);
            *(float2*)(p + 2) = make_float2(v4.z, v4.w);
        } else {
            #pragma unroll
            for (int rep = 0; rep < 2; ++rep) {
                const int idx = lu * 2 + rep;
                const int r = idx >> 1, half = idx & 1;
                const int gk = r + 1;
                float4 v4 = *(const float4*)&g_v[gk * 32 + c * 8 + half * 4];
                *(float4*)&vsb[r * 8 + half * 4] = v4;
            }
        }
    }

    for (int kb = 0; kb <= qb; ++kb) {
        const int k0 = kb * 64;
        const int buf = kb & 1;
        const float* ks  = ksb + buf * 960;
        const float* vsm = vsb + buf * 512;
        __syncthreads();   // loads for this tile done; prev score done with G

        // ---- G compute: 6x6 block per thread, d in float2 pairs ----
        {
            float gacc[6][6] = {};
            #pragma unroll
            for (int dp = 0; dp < 4; ++dp) {
                float2 qd[6], kd[6];
                #pragma unroll
                for (int ii = 0; ii < 6; ++ii)
                    qd[ii] = *(const float2*)&qs[(i0 + ii) * 8 + dp * 2];
                #pragma unroll
                for (int jj = 0; jj < 6; ++jj)
                    kd[jj] = *(const float2*)&ks[(j0 + jj) * 10 + dp * 2];
                #pragma unroll
                for (int ii = 0; ii < 6; ++ii)
                    #pragma unroll
                    for (int jj = 0; jj < 6; ++jj) {
                        gacc[ii][jj] = fmaf(qd[ii].x, kd[jj].x, gacc[ii][jj]);
                        gacc[ii][jj] = fmaf(qd[ii].y, kd[jj].y, gacc[ii][jj]);
                    }
            }
            #pragma unroll
            for (int ii = 0; ii < 6; ++ii)
                #pragma unroll
                for (int jj = 0; jj < 6; ++jj)
                    G[(i0 + ii) * GSTR + (j0 + jj)] = gacc[ii][jj];
        }
        __syncthreads();

        // ---- diagonal prefix (threads 0..190); v-prefetch (192..255) ----
        if (t < 191) {
            const int dlt = t - 95;
            const int ad  = dlt < 0 ? -dlt : dlt;
            const int L   = 96 - ad;
            int off = (dlt > 0) ? dlt * GSTR : -dlt;
            float carry = 0.0f;
            int s = 0;
            for (; s + 4 <= L; s += 4) {
                const float e0 = G[off];
                const float e1 = G[off + (GSTR + 1)];
                const float e2 = G[off + 2 * (GSTR + 1)];
                const float e3 = G[off + 3 * (GSTR + 1)];
                const float c0 = carry + e0;
                const float c1 = c0 + e1;
                const float c2 = c1 + e2;
                const float c3 = c2 + e3;
                G[off] = c0;
                G[off + (GSTR + 1)]     = c1;
                G[off + 2 * (GSTR + 1)] = c2;
                G[off + 3 * (GSTR + 1)] = c3;
                carry = c3;
                off += 4 * (GSTR + 1);
            }
            for (; s < L; ++s) { carry += G[off]; G[off] = carry; off += GSTR + 1; }
        } else if (t >= 192 && kb < qb) {
            const int nk0 = k0 + 64;
            #pragma unroll
            for (int rep = 0; rep < 2; ++rep) {
                const int idx = lu * 2 + rep;
                const int r = idx >> 1, half = idx & 1;
                const int gk = nk0 + r + 1;
                float4 v4 = make_float4(0.f, 0.f, 0.f, 0.f);
                if (gk < SEQ) v4 = *(const float4*)&g_v[gk * 32 + c * 8 + half * 4];
                *(float4*)&vsb[(buf ^ 1) * 512 + r * 8 + half * 4] = v4;
            }
        }
        __syncthreads();

        // ---- k-halo prefetch for next tile (overlaps score phase) ----
        if (kb < qb && t < 192) {
            const int gk = k0 + 64 - 31 + lr;
            const float4 v4 = *(const float4*)&g_k[gk * 32 + c * 8 + lhalf * 4];
            float* p = &ksb[(buf ^ 1) * 960 + lr * 10 + lhalf * 4];
            *(float2*)(p)     = make_float2(v4.x, v4.y);
            *(float2*)(p + 2) = make_float2(v4.z, v4.w);
        }

        // ---- scores + single-pass online softmax ----
        float sv[16];
        float tmax = NEGINF;
        const int browH = (a + 31) * GSTR + 31;
        const int browL = (a - 1) * GSTR - 1;
        #pragma unroll
        for (int bb = 0; bb < 16; ++bb) {
            const int b  = (bb << 2) | jq;
            const int kg = k0 + b;
            float s = NEGINF;
            if (kg < qg) {
                const float hi = G[browH + b];
                const float lo = (a > 0 && b > 0) ? G[browL + b] : 0.0f;
                s = (hi - lo) * scale + (float)kg * bias_r;
            }
            sv[bb] = s;
            tmax = fmaxf(tmax, s);
        }
        if (tmax > NEGINF) {
            const float nm = fmaxf(m_run, tmax);
            if (m_run > NEGINF && nm > m_run) {
                const float f = __expf(m_run - nm);
                l_run *= f;
                #pragma unroll
                for (int d = 0; d < 8; ++d) acc[d] *= f;
            }
            m_run = nm;
            #pragma unroll
            for (int bb = 0; bb < 16; ++bb) {
                if (sv[bb] > NEGINF) {
                    const float e = __expf(sv[bb] - m_run);
                    l_run += e;
                    const int b = (bb << 2) | jq;
                    const float4 v0 = *(const float4*)&vsm[b * 8];
                    const float4 v1 = *(const float4*)&vsm[b * 8 + 4];
                    acc[0] = fmaf(e, v0.x, acc[0]); acc[1] = fmaf(e, v0.y, acc[1]);
                    acc[2] = fmaf(e, v0.z, acc[2]); acc[3] = fmaf(e, v0.w, acc[3]);
                    acc[4] = fmaf(e, v1.x, acc[4]); acc[5] = fmaf(e, v1.y, acc[5]);
                    acc[6] = fmaf(e, v1.z, acc[6]); acc[7] = fmaf(e, v1.w, acc[7]);
                }
            }
        }
    }

    // merge the 4 threads of each query row
    #pragma unroll
    for (int off = 1; off < 4; off <<= 1) {
        const float mo  = __shfl_xor_sync(0xffffffffu, m_run, off);
        const float lo2 = __shfl_xor_sync(0xffffffffu, l_run, off);
        const float nm = fmaxf(m_run, mo);
        const float f1 = (m_run > NEGINF) ? __expf(m_run - nm) : 0.0f;
        const float f2 = (mo    > NEGINF) ? __expf(mo    - nm) : 0.0f;
        l_run = l_run * f1 + lo2 * f2;
        #pragma unroll
        for (int d = 0; d < 8; ++d) {
            const float ao = __shfl_xor_sync(0xffffffffu, acc[d], off);
            acc[d] = acc[d] * f1 + ao * f2;
        }
        m_run = nm;
    }
    if (jq == 0) {
        const float invl = (l_run > 0.0f) ? 1.0f / l_run : 0.0f;
        #pragma unroll
        for (int d = 0; d < 8; ++d) {
            const int f = h * 8 + d;
            const float e0 = ve0[f], e1 = ve1[f];
            const float o  = acc[d] * invl;
            g_attn[qg * 128 + f] = o * (e1 - e0) + e0;   // affine folded here
        }
    }
}

// ---------------- Pass C: output projection (pure GEMM, pipelined) ----------------
// out[m][n] = sum_j g_attn[m][j] * Wo[n][j]   (M=N=2048, K=128)
__global__ __launch_bounds__(256) void out_kernel(
    const float* __restrict__ Wo,
    float* __restrict__ out)
{
    __shared__ float As[16][132];
    __shared__ float Bs[16][68];
    const int m0 = blockIdx.x * 128;
    const int n0 = blockIdx.y * 64;
    const int t  = threadIdx.x;

    const int arow = t >> 1;
    const int akA  = (t & 1) * 4;
    const int brow = t >> 2;
    const int bk   = (t & 3) * 4;
    const float* ar_ = g_attn + (size_t)(m0 + arow) * 128;
    const float* br_ = Wo + (size_t)(n0 + brow) * 128;

    const int tyy = t >> 4, txx = t & 15;
    const int i0 = tyy * 8, j0 = txx * 4;

    float4 a0 = *(const float4*)(ar_ + akA);
    float4 a1 = *(const float4*)(ar_ + akA + 8);
    float4 b0 = *(const float4*)(br_ + bk);

    float acc[8][4] = {};
    for (int k0 = 0; k0 < 128; k0 += 16) {
        __syncthreads();
        As[akA + 0][arow] = a0.x; As[akA + 1][arow] = a0.y;
        As[akA + 2][arow] = a0.z; As[akA + 3][arow] = a0.w;
        As[akA + 8][arow] = a1.x; As[akA + 9][arow] = a1.y;
        As[akA +10][arow] = a1.z; As[akA +11][arow] = a1.w;
        Bs[bk + 0][brow] = b0.x; Bs[bk + 1][brow] = b0.y;
        Bs[bk + 2][brow] = b0.z; Bs[bk + 3][brow] = b0.w;
        __syncthreads();
        if (k0 + 16 < 128) {
            a0 = *(const float4*)(ar_ + k0 + 16 + akA);
            a1 = *(const float4*)(ar_ + k0 + 16 + akA + 8);
            b0 = *(const float4*)(br_ + k0 + 16 + bk);
        }
        #pragma unroll
        for (int kk = 0; kk < 16; ++kk) {
            const float4 av0 = *(const float4*)&As[kk][i0];
            const float4 av1 = *(const float4*)&As[kk][i0 + 4];
            const float4 bv  = *(const float4*)&Bs[kk][j0];
            float ar[8] = {av0.x, av0.y, av0.z, av0.w, av1.x, av1.y, av1.z, av1.w};
            float br[4] = {bv.x, bv.y, bv.z, bv.w};
            #pragma unroll
            for (int i = 0; i < 8; ++i)
                #pragma unroll
                for (int j = 0; j < 4; ++j)
                    acc[i][j] = fmaf(ar[i], br[j], acc[i][j]);
        }
    }
    #pragma unroll
    for (int i = 0; i < 8; ++i) {
        float4 o = make_float4(acc[i][0], acc[i][1], acc[i][2], acc[i][3]);
        *(float4*)&out[(size_t)(m0 + i0 + i) * DMODEL + n0 + j0] = o;
    }
}

// ---------------- launch ----------------
extern "C" void kernel_launch(void* const* d_in, const int* in_sizes, int n_in,
                              void* d_out, int out_size)
{
    const float* X   = (const float*)d_in[0];
    const float* Wq  = (const float*)d_in[1];
    const float* Wk  = (const float*)d_in[2];
    const float* Wv  = (const float*)d_in[3];
    const float* Wo  = (const float*)d_in[4];
    const float* ve0 = (const float*)d_in[5];
    const float* ve1 = (const float*)d_in[6];
    const float* tau = (const float*)d_in[7];
    float* out = (float*)d_out;
    (void)in_sizes; (void)n_in; (void)out_size;

    cudaFuncSetAttribute(attn_kernel,
                         cudaFuncAttributeMaxDynamicSharedMemorySize,
                         SMEM_FLOATS * (int)sizeof(float));

    proj_partial<<<dim3(16, 3, 8), 256>>>(X, Wq, Wk, Wv);
    proj_reduce <<<1536, 256>>>(tau);
    attn_kernel <<<dim3(32, 16), 256, SMEM_FLOATS * sizeof(float)>>>(tau, ve0, ve1);
    out_kernel  <<<dim3(16, 32), 256>>>(Wo, out);
}